// round 1
// baseline (speedup 1.0000x reference)
#include <cuda_runtime.h>

#define CB 2
#define CC 128
#define CCK 64
#define CH 256
#define CW 512
#define CH2 128
#define CW2 256
#define HWF (CH*CW)       // 131072
#define HW2 (CH2*CW2)     // 32768
#define NPIXF (CB*HWF)    // 262144
#define NPIX2 (CB*HW2)    // 65536

#define CTY 4
#define CTX 16
#define HY (CTY+2)        // 6
#define HX (CTX+2)        // 18
#define NH (HY*HX)        // 108

// Scratch (device globals: allocation-free)
__device__ float g_k[NPIX2*CCK];            // coarse k, NHWC [p][64]
__device__ float g_v[NPIX2*CC];             // coarse v, NHWC [p][128]
__device__ float g_q[(size_t)NPIXF*CCK];    // fine q, NHWC [p][64]
__device__ float g_x[(size_t)NPIXF*CC];     // attention out, NHWC [p][128]
__device__ float g_Wc[CC*CC];               // Wout @ Wvi
__device__ float g_beff[CC];                // Wout @ bvi + bout

// ---------------------------------------------------------------------------
// K0: fuse weights  Wc = Wout @ Wvi, beff = Wout @ bvi + bout
// ---------------------------------------------------------------------------
__global__ void k_fuse(const float* __restrict__ Wout, const float* __restrict__ Wvi,
                       const float* __restrict__ bvi, const float* __restrict__ bout) {
    int o = blockIdx.x, i = threadIdx.x;
    float acc = 0.f;
    for (int m = 0; m < CC; m++) acc += Wout[o*CC + m] * Wvi[m*CC + i];
    g_Wc[o*CC + i] = acc;
    if (i == 0) {
        float b = bout[o];
        for (int m = 0; m < CC; m++) b += Wout[o*CC + m] * bvi[m];
        g_beff[o] = b;
    }
}

// ---------------------------------------------------------------------------
// K1: coarse k,v = [Wk; Wvp] @ h_prev   (192 out channels, 64 px per block)
// smem: Ws[192][132] + Xs[128][64] = 134144 B
// ---------------------------------------------------------------------------
__global__ void k_kv(const float* __restrict__ hp,
                     const float* __restrict__ Wk, const float* __restrict__ bk,
                     const float* __restrict__ Wvp, const float* __restrict__ bvp) {
    extern __shared__ float sm[];
    float* Ws = sm;             // 192 x 132 (padded)
    float* Xs = sm + 192*132;   // 128 x 64
    int t = threadIdx.x;

    for (int idx = t; idx < 192*CC; idx += 256) {
        int r = idx >> 7, c = idx & 127;
        Ws[r*132 + c] = (r < CCK) ? Wk[r*CC + c] : Wvp[(r - CCK)*CC + c];
    }
    int p0 = blockIdx.x * 64;
    int b = p0 / HW2, s0 = p0 % HW2;
    const float* base = hp + (size_t)b*CC*HW2 + s0;
    for (int idx = t; idx < CC*64; idx += 256) {
        int c = idx >> 6, p = idx & 63;
        Xs[c*64 + p] = base[(size_t)c*HW2 + p];
    }
    __syncthreads();

    int ty = t >> 4, tx = t & 15;
    float acc[12][4];
    #pragma unroll
    for (int i = 0; i < 12; i++)
        #pragma unroll
        for (int j = 0; j < 4; j++) acc[i][j] = 0.f;

    for (int k = 0; k < CC; k++) {
        float xv[4];
        #pragma unroll
        for (int j = 0; j < 4; j++) xv[j] = Xs[k*64 + tx + 16*j];
        #pragma unroll
        for (int i = 0; i < 12; i++) {
            float wv = Ws[(ty + 16*i)*132 + k];
            #pragma unroll
            for (int j = 0; j < 4; j++) acc[i][j] += wv * xv[j];
        }
    }
    __syncthreads();

    float* Os = sm;  // 192 x 65, aliases Ws (done with it)
    #pragma unroll
    for (int i = 0; i < 12; i++) {
        int r = ty + 16*i;
        float bias = (r < CCK) ? bk[r] : bvp[r - CCK];
        #pragma unroll
        for (int j = 0; j < 4; j++) Os[r*65 + tx + 16*j] = acc[i][j] + bias;
    }
    __syncthreads();

    float* gk = g_k + (size_t)p0*CCK;
    for (int idx = t; idx < CCK*64; idx += 256) {
        int p = idx >> 6, c = idx & 63;
        gk[p*CCK + c] = Os[c*65 + p];
    }
    float* gv = g_v + (size_t)p0*CC;
    for (int idx = t; idx < CC*64; idx += 256) {
        int p = idx >> 7, c = idx & 127;
        gv[p*CC + c] = Os[(CCK + c)*65 + p];
    }
}

// ---------------------------------------------------------------------------
// K2: q = Wq @ h_init   (64 out channels, 64 px per block)
// smem: Ws[64][132] + Xs[128][64] = 66560 B
// ---------------------------------------------------------------------------
__global__ void k_q(const float* __restrict__ hi,
                    const float* __restrict__ Wq, const float* __restrict__ bq) {
    extern __shared__ float sm[];
    float* Ws = sm;            // 64 x 132
    float* Xs = sm + 64*132;   // 128 x 64
    int t = threadIdx.x;

    for (int idx = t; idx < CCK*CC; idx += 256) {
        int r = idx >> 7, c = idx & 127;
        Ws[r*132 + c] = Wq[idx];
    }
    int p0 = blockIdx.x * 64;
    int b = p0 / HWF, s0 = p0 % HWF;
    const float* base = hi + (size_t)b*CC*HWF + s0;
    for (int idx = t; idx < CC*64; idx += 256) {
        int c = idx >> 6, p = idx & 63;
        Xs[c*64 + p] = base[(size_t)c*HWF + p];
    }
    __syncthreads();

    int ty = t >> 4, tx = t & 15;
    float acc[4][4];
    #pragma unroll
    for (int i = 0; i < 4; i++)
        #pragma unroll
        for (int j = 0; j < 4; j++) acc[i][j] = 0.f;

    for (int k = 0; k < CC; k++) {
        float xv[4];
        #pragma unroll
        for (int j = 0; j < 4; j++) xv[j] = Xs[k*64 + tx + 16*j];
        #pragma unroll
        for (int i = 0; i < 4; i++) {
            float wv = Ws[(ty + 16*i)*132 + k];
            #pragma unroll
            for (int j = 0; j < 4; j++) acc[i][j] += wv * xv[j];
        }
    }
    __syncthreads();

    float* Os = sm;  // 64 x 65, aliases Ws
    #pragma unroll
    for (int i = 0; i < 4; i++) {
        int r = ty + 16*i;
        float bias = bq[r];
        #pragma unroll
        for (int j = 0; j < 4; j++) Os[r*65 + tx + 16*j] = acc[i][j] + bias;
    }
    __syncthreads();

    float* gq = g_q + (size_t)p0*CCK;
    for (int idx = t; idx < CCK*64; idx += 256) {
        int p = idx >> 6, c = idx & 63;
        gq[p*CCK + c] = Os[c*65 + p];
    }
}

// ---------------------------------------------------------------------------
// K3: attention. Block = 4x16 coarse tile (8x32 fine = 256 fine pixels).
// smem: ks[108][68] + vs[108][132] + qs[256][65] + as[256][12] = 165248 B
// Zero-filled halo taps reproduce unfold's zero-padding semantics exactly.
// ---------------------------------------------------------------------------
__global__ void k_attn() {
    extern __shared__ float sm[];
    float* ks = sm;                 // NH x 68
    float* vs = ks + NH*68;         // NH x 132
    float* qs = vs + NH*132;        // 256 x 65
    float* as = qs + 256*65;        // 256 x 12
    int t = threadIdx.x;
    int b = blockIdx.z;
    int cy0 = blockIdx.y * CTY, cx0 = blockIdx.x * CTX;

    for (int idx = t; idx < NH*CCK; idx += 256) {
        int pix = idx >> 6, c = idx & 63;
        int hy = pix / HX, hx = pix % HX;
        int gy = cy0 + hy - 1, gx = cx0 + hx - 1;
        float v = 0.f;
        if ((unsigned)gy < CH2 && (unsigned)gx < CW2)
            v = g_k[((size_t)(b*HW2 + gy*CW2 + gx))*CCK + c];
        ks[pix*68 + c] = v;
    }
    for (int idx = t; idx < NH*CC; idx += 256) {
        int pix = idx >> 7, c = idx & 127;
        int hy = pix / HX, hx = pix % HX;
        int gy = cy0 + hy - 1, gx = cx0 + hx - 1;
        float v = 0.f;
        if ((unsigned)gy < CH2 && (unsigned)gx < CW2)
            v = g_v[((size_t)(b*HW2 + gy*CW2 + gx))*CC + c];
        vs[pix*132 + c] = v;
    }
    int fy0 = cy0*2, fx0 = cx0*2;
    for (int idx = t; idx < 256*CCK; idx += 256) {
        int p = idx >> 6, c = idx & 63;
        int fy = p >> 5, fx = p & 31;
        qs[p*65 + c] = g_q[((size_t)((b*CH + fy0 + fy)*CW + fx0 + fx))*CCK + c];
    }
    __syncthreads();

    // Phase A: one thread per fine pixel: 9 scores + softmax
    {
        int p = t;
        int fy = p >> 5, fx = p & 31;
        int cy = fy >> 1, cx = fx >> 1;
        float sc[9];
        #pragma unroll
        for (int j = 0; j < 9; j++) sc[j] = 0.f;
        const float* qp = qs + p*65;
        for (int c = 0; c < CCK; c++) {
            float qv = qp[c];
            #pragma unroll
            for (int dy = 0; dy < 3; dy++)
                #pragma unroll
                for (int dx = 0; dx < 3; dx++)
                    sc[dy*3 + dx] += qv * ks[((cy + dy)*HX + cx + dx)*68 + c];
        }
        float m = sc[0];
        #pragma unroll
        for (int j = 1; j < 9; j++) m = fmaxf(m, sc[j]);
        float s = 0.f;
        #pragma unroll
        for (int j = 0; j < 9; j++) { sc[j] = __expf(sc[j] - m); s += sc[j]; }
        float inv = 1.f / s;
        #pragma unroll
        for (int j = 0; j < 9; j++) as[p*12 + j] = sc[j]*inv;
    }
    __syncthreads();

    // Phase B: 256 px x 128 ch outputs, channel-contiguous (coalesced, conflict-free)
    for (int it = 0; it < 128; it++) {
        int oidx = it*256 + t;
        int c = oidx & 127, p = oidx >> 7;
        int fy = p >> 5, fx = p & 31;
        int cy = fy >> 1, cx = fx >> 1;
        const float* ap = as + p*12;
        float acc = 0.f;
        #pragma unroll
        for (int dy = 0; dy < 3; dy++)
            #pragma unroll
            for (int dx = 0; dx < 3; dx++)
                acc += ap[dy*3 + dx] * vs[((cy + dy)*HX + cx + dx)*132 + c];
        g_x[((size_t)((b*CH + fy0 + fy)*CW + fx0 + fx))*CC + c] = acc;
    }
}

// ---------------------------------------------------------------------------
// K4: out = [Wc | Wout] @ [h_init; x] + beff   (K=256 GEMM, 64 px per block)
// smem: Wf[128][260] + Ys[256][65] = 199680 B
// ---------------------------------------------------------------------------
__global__ void k_out(const float* __restrict__ hi, const float* __restrict__ Wout,
                      float* __restrict__ out) {
    extern __shared__ float sm[];
    float* Wf = sm;             // 128 x 260
    float* Ys = sm + 128*260;   // 256 x 65
    int t = threadIdx.x;

    for (int idx = t; idx < CC*CC; idx += 256) {
        int o = idx >> 7, i = idx & 127;
        Wf[o*260 + i]        = g_Wc[idx];
        Wf[o*260 + 128 + i]  = Wout[idx];
    }
    int p0 = blockIdx.x * 64;
    int b = p0 / HWF, s0 = p0 % HWF;
    const float* base = hi + (size_t)b*CC*HWF + s0;
    for (int idx = t; idx < CC*64; idx += 256) {
        int c = idx >> 6, p = idx & 63;
        Ys[c*65 + p] = base[(size_t)c*HWF + p];
    }
    const float* xb = g_x + (size_t)p0*CC;
    for (int idx = t; idx < CC*64; idx += 256) {
        int c = idx & 127, p = idx >> 7;
        Ys[(CC + c)*65 + p] = xb[p*CC + c];
    }
    __syncthreads();

    int ty = t >> 4, tx = t & 15;
    float acc[8][4];
    #pragma unroll
    for (int i = 0; i < 8; i++)
        #pragma unroll
        for (int j = 0; j < 4; j++) acc[i][j] = 0.f;

    for (int k = 0; k < 256; k++) {
        float yv[4];
        #pragma unroll
        for (int j = 0; j < 4; j++) yv[j] = Ys[k*65 + tx + 16*j];
        #pragma unroll
        for (int i = 0; i < 8; i++) {
            float wv = Wf[(ty + 16*i)*260 + k];
            #pragma unroll
            for (int j = 0; j < 4; j++) acc[i][j] += wv * yv[j];
        }
    }

    float* ob = out + (size_t)b*CC*HWF + s0;
    #pragma unroll
    for (int i = 0; i < 8; i++) {
        int r = ty + 16*i;
        float bb = g_beff[r];
        #pragma unroll
        for (int j = 0; j < 4; j++) ob[(size_t)r*HWF + tx + 16*j] = acc[i][j] + bb;
    }
}

// ---------------------------------------------------------------------------
extern "C" void kernel_launch(void* const* d_in, const int* in_sizes, int n_in,
                              void* d_out, int out_size) {
    const float* h_prev = (const float*)d_in[0];
    const float* h_init = (const float*)d_in[1];
    const float* Wq   = (const float*)d_in[2];
    const float* bq   = (const float*)d_in[3];
    const float* Wk   = (const float*)d_in[4];
    const float* bk   = (const float*)d_in[5];
    const float* Wvp  = (const float*)d_in[6];
    const float* bvp  = (const float*)d_in[7];
    const float* Wvi  = (const float*)d_in[8];
    const float* bvi  = (const float*)d_in[9];
    const float* Wout = (const float*)d_in[10];
    const float* bout = (const float*)d_in[11];
    float* out = (float*)d_out;

    cudaFuncSetAttribute(k_kv,   cudaFuncAttributeMaxDynamicSharedMemorySize, 134144);
    cudaFuncSetAttribute(k_q,    cudaFuncAttributeMaxDynamicSharedMemorySize, 66560);
    cudaFuncSetAttribute(k_attn, cudaFuncAttributeMaxDynamicSharedMemorySize, 165248);
    cudaFuncSetAttribute(k_out,  cudaFuncAttributeMaxDynamicSharedMemorySize, 199680);

    k_fuse<<<CC, CC>>>(Wout, Wvi, bvi, bout);
    k_kv<<<NPIX2/64, 256, 134144>>>(h_prev, Wk, bk, Wvp, bvp);
    k_q<<<NPIXF/64, 256, 66560>>>(h_init, Wq, bq);
    dim3 ag(CW2/CTX, CH2/CTY, CB);
    k_attn<<<ag, 256, 165248>>>();
    k_out<<<NPIXF/64, 256, 199680>>>(h_init, Wout, out);
}

// round 2
// speedup vs baseline: 1.2395x; 1.2395x over previous
#include <cuda_runtime.h>

#define CB 2
#define CC 128
#define CCK 64
#define CH 256
#define CW 512
#define CH2 128
#define CW2 256
#define HWF (CH*CW)       // 131072
#define HW2 (CH2*CW2)     // 32768
#define NPIXF (CB*HWF)    // 262144
#define NPIX2 (CB*HW2)    // 65536

#define CTY 4
#define CTX 16
#define HY (CTY+2)        // 6
#define HX (CTX+2)        // 18
#define NH (HY*HX)        // 108

typedef unsigned long long ull;

// ---- f32x2 packed-math helpers (sm_103a FFMA2 path) ----
__device__ __forceinline__ ull fma2(ull a, ull b, ull c) {
    ull d;
    asm("fma.rn.f32x2 %0, %1, %2, %3;" : "=l"(d) : "l"(a), "l"(b), "l"(c));
    return d;
}
__device__ __forceinline__ ull pk2(float x) {          // broadcast {x,x}
    ull r;
    asm("mov.b64 %0, {%1, %1};" : "=l"(r) : "f"(x));
    return r;
}
__device__ __forceinline__ ull pk2p(float x, float y) { // pack {x,y}
    ull r;
    asm("mov.b64 %0, {%1, %2};" : "=l"(r) : "f"(x), "f"(y));
    return r;
}
__device__ __forceinline__ float2 upk(ull v) {
    float2 o;
    asm("mov.b64 {%0, %1}, %2;" : "=f"(o.x), "=f"(o.y) : "l"(v));
    return o;
}
__device__ __forceinline__ ull ld2(const float* p) {   // LDS.64 / LDG.64
    return *reinterpret_cast<const ull*>(p);
}

// Scratch (device globals: allocation-free)
__device__ float g_k[NPIX2*CCK];            // coarse k, NHWC [p][64]
__device__ float g_v[NPIX2*CC];             // coarse v, NHWC [p][128]
__device__ float g_q[(size_t)NPIXF*CCK];    // fine q, NHWC [p][64]
__device__ float g_x[(size_t)NPIXF*CC];     // attention out, NHWC [p][128]
__device__ float g_Wc[CC*CC];               // Wout @ Wvi
__device__ float g_beff[CC];                // Wout @ bvi + bout

// ---------------------------------------------------------------------------
// K0: fuse weights  Wc = Wout @ Wvi, beff = Wout @ bvi + bout
// ---------------------------------------------------------------------------
__global__ void k_fuse(const float* __restrict__ Wout, const float* __restrict__ Wvi,
                       const float* __restrict__ bvi, const float* __restrict__ bout) {
    int o = blockIdx.x, i = threadIdx.x;
    float acc = 0.f;
    for (int m = 0; m < CC; m++) acc += Wout[o*CC + m] * Wvi[m*CC + i];
    g_Wc[o*CC + i] = acc;
    if (i == 0) {
        float b = bout[o];
        for (int m = 0; m < CC; m++) b += Wout[o*CC + m] * bvi[m];
        g_beff[o] = b;
    }
}

// ---------------------------------------------------------------------------
// K1: coarse k,v = [Wk; Wvp] @ h_prev. 192 out ch, 64 px/block, f32x2 math.
// Wt transposed [k=128][r=192] pitch 194; Xs [128][64]; smem = 132096 B
// ---------------------------------------------------------------------------
#define KV_WP 194
__global__ void k_kv(const float* __restrict__ hp,
                     const float* __restrict__ Wk, const float* __restrict__ bk,
                     const float* __restrict__ Wvp, const float* __restrict__ bvp) {
    extern __shared__ float sm[];
    float* Wt = sm;                 // [128][194]
    float* Xs = sm + 128*KV_WP;     // [128][64]
    int t = threadIdx.x;

    for (int idx = t; idx < 192*CC; idx += 256) {
        int r = idx >> 7, k = idx & 127;
        float w = (r < CCK) ? Wk[r*CC + k] : Wvp[(r - CCK)*CC + k];
        Wt[k*KV_WP + r] = w;
    }
    int p0 = blockIdx.x * 64;
    int b = p0 / HW2, s0 = p0 % HW2;
    const float* base = hp + (size_t)b*CC*HW2 + s0;
    for (int idx = t; idx < CC*64; idx += 256) {
        int c = idx >> 6, p = idx & 63;
        Xs[c*64 + p] = base[(size_t)c*HW2 + p];
    }
    __syncthreads();

    int ty = t >> 4, tx = t & 15;            // ty: 16 ch-groups(12ch=6 pairs), tx: 16 px-groups(4 px)
    ull acc[6][4];
    #pragma unroll
    for (int i = 0; i < 6; i++) {
        int r = 2*ty + 32*i;
        ull binit = (r < CCK) ? ld2(&bk[r]) : ld2(&bvp[r - CCK]);
        #pragma unroll
        for (int j = 0; j < 4; j++) acc[i][j] = binit;
    }
    for (int k = 0; k < CC; k++) {
        ull yv[4];
        #pragma unroll
        for (int j = 0; j < 4; j++) yv[j] = pk2(Xs[k*64 + tx + 16*j]);
        #pragma unroll
        for (int i = 0; i < 6; i++) {
            ull wv = ld2(&Wt[k*KV_WP + 2*ty + 32*i]);
            #pragma unroll
            for (int j = 0; j < 4; j++) acc[i][j] = fma2(wv, yv[j], acc[i][j]);
        }
    }
    __syncthreads();

    float* Os = sm;  // [192][65], aliases Wt
    #pragma unroll
    for (int i = 0; i < 6; i++) {
        int r = 2*ty + 32*i;
        #pragma unroll
        for (int j = 0; j < 4; j++) {
            float2 v = upk(acc[i][j]);
            Os[r*65 + tx + 16*j]       = v.x;
            Os[(r + 1)*65 + tx + 16*j] = v.y;
        }
    }
    __syncthreads();

    float* gk = g_k + (size_t)p0*CCK;
    for (int idx = t; idx < CCK*64; idx += 256) {
        int p = idx >> 6, c = idx & 63;
        gk[p*CCK + c] = Os[c*65 + p];
    }
    float* gv = g_v + (size_t)p0*CC;
    for (int idx = t; idx < CC*64; idx += 256) {
        int p = idx >> 7, c = idx & 127;
        gv[p*CC + c] = Os[(CCK + c)*65 + p];
    }
}

// ---------------------------------------------------------------------------
// K2: q = Wq @ h_init. 64 out ch, 64 px/block, f32x2 math.
// Wt [128][66] + Xs [128][64]; smem = 66560 B
// ---------------------------------------------------------------------------
#define Q_WP 66
__global__ void k_q(const float* __restrict__ hi,
                    const float* __restrict__ Wq, const float* __restrict__ bq) {
    extern __shared__ float sm[];
    float* Wt = sm;                // [128][66]
    float* Xs = sm + 128*Q_WP;     // [128][64]
    int t = threadIdx.x;

    for (int idx = t; idx < CCK*CC; idx += 256) {
        int r = idx >> 7, k = idx & 127;
        Wt[k*Q_WP + r] = Wq[r*CC + k];
    }
    int p0 = blockIdx.x * 64;
    int b = p0 / HWF, s0 = p0 % HWF;
    const float* base = hi + (size_t)b*CC*HWF + s0;
    for (int idx = t; idx < CC*64; idx += 256) {
        int c = idx >> 6, p = idx & 63;
        Xs[c*64 + p] = base[(size_t)c*HWF + p];
    }
    __syncthreads();

    int ty = t >> 5, tx = t & 31;  // ty: 8 ch-groups(8ch=4 pairs), tx: 32 px-groups(2 px)
    ull acc[4][2];
    #pragma unroll
    for (int i = 0; i < 4; i++) {
        ull binit = ld2(&bq[2*ty + 16*i]);
        #pragma unroll
        for (int j = 0; j < 2; j++) acc[i][j] = binit;
    }
    for (int k = 0; k < CC; k++) {
        ull yv[2];
        #pragma unroll
        for (int j = 0; j < 2; j++) yv[j] = pk2(Xs[k*64 + tx + 32*j]);
        #pragma unroll
        for (int i = 0; i < 4; i++) {
            ull wv = ld2(&Wt[k*Q_WP + 2*ty + 16*i]);
            #pragma unroll
            for (int j = 0; j < 2; j++) acc[i][j] = fma2(wv, yv[j], acc[i][j]);
        }
    }
    __syncthreads();

    float* Os = sm;  // [64][65], aliases Wt
    #pragma unroll
    for (int i = 0; i < 4; i++) {
        int r = 2*ty + 16*i;
        #pragma unroll
        for (int j = 0; j < 2; j++) {
            float2 v = upk(acc[i][j]);
            Os[r*65 + tx + 32*j]       = v.x;
            Os[(r + 1)*65 + tx + 32*j] = v.y;
        }
    }
    __syncthreads();

    float* gq = g_q + (size_t)p0*CCK;
    for (int idx = t; idx < CCK*64; idx += 256) {
        int p = idx >> 6, c = idx & 63;
        gq[p*CCK + c] = Os[c*65 + p];
    }
}

// ---------------------------------------------------------------------------
// K3: attention. Block = 4x16 coarse tile (8x32 fine = 256 px). f32x2 math.
// smem: ks[108][66] + vs[108][132] + as[256][12] = 97824 B  -> 2 blocks/SM
// q streamed from gmem (no smem tile). Zero halo == unfold zero-padding.
// ---------------------------------------------------------------------------
#define KP 66
#define VP 132
__global__ void k_attn() {
    extern __shared__ float sm[];
    float* ks = sm;                 // [108][66]
    float* vs = ks + NH*KP;         // [108][132]
    float* as = vs + NH*VP;         // [256][12]
    int t = threadIdx.x;
    int b = blockIdx.z;
    int cy0 = blockIdx.y * CTY, cx0 = blockIdx.x * CTX;
    int fy0 = cy0*2, fx0 = cx0*2;

    for (int idx = t; idx < NH*CCK; idx += 256) {
        int pix = idx >> 6, c = idx & 63;
        int hy = pix / HX, hx = pix % HX;
        int gy = cy0 + hy - 1, gx = cx0 + hx - 1;
        float v = 0.f;
        if ((unsigned)gy < CH2 && (unsigned)gx < CW2)
            v = g_k[((size_t)(b*HW2 + gy*CW2 + gx))*CCK + c];
        ks[pix*KP + c] = v;
    }
    for (int idx = t; idx < NH*CC; idx += 256) {
        int pix = idx >> 7, c = idx & 127;
        int hy = pix / HX, hx = pix % HX;
        int gy = cy0 + hy - 1, gx = cx0 + hx - 1;
        float v = 0.f;
        if ((unsigned)gy < CH2 && (unsigned)gx < CW2)
            v = g_v[((size_t)(b*HW2 + gy*CW2 + gx))*CC + c];
        vs[pix*VP + c] = v;
    }
    __syncthreads();

    // Phase A: one thread per fine pixel; q streamed from gmem (float4),
    // 9 packed scores + softmax.
    {
        int p = t;
        int fy = p >> 5, fx = p & 31;
        int cy = fy >> 1, cx = fx >> 1;
        const float4* gq = reinterpret_cast<const float4*>(
            g_q + ((size_t)((b*CH + fy0 + fy)*CW + fx0 + fx))*CCK);
        const float* kb = ks + (cy*HX + cx)*KP;
        ull sc2[9];
        #pragma unroll
        for (int j = 0; j < 9; j++) sc2[j] = 0ull;
        #pragma unroll 4
        for (int cc = 0; cc < 16; cc++) {
            float4 q4 = gq[cc];
            ull qa = pk2p(q4.x, q4.y);
            ull qb = pk2p(q4.z, q4.w);
            int c = cc*4;
            #pragma unroll
            for (int dy = 0; dy < 3; dy++)
                #pragma unroll
                for (int dx = 0; dx < 3; dx++) {
                    int j = dy*3 + dx;
                    const float* kp = kb + (dy*HX + dx)*KP + c;
                    sc2[j] = fma2(qa, ld2(kp), sc2[j]);
                    sc2[j] = fma2(qb, ld2(kp + 2), sc2[j]);
                }
        }
        float sc[9];
        #pragma unroll
        for (int j = 0; j < 9; j++) { float2 v = upk(sc2[j]); sc[j] = v.x + v.y; }
        float m = sc[0];
        #pragma unroll
        for (int j = 1; j < 9; j++) m = fmaxf(m, sc[j]);
        float s = 0.f;
        #pragma unroll
        for (int j = 0; j < 9; j++) { sc[j] = __expf(sc[j] - m); s += sc[j]; }
        float inv = 1.f / s;
        #pragma unroll
        for (int j = 0; j < 9; j++) as[p*12 + j] = sc[j]*inv;
    }
    __syncthreads();

    // Phase B: 32 passes; each pass: 8 px x 128 ch. Thread owns (px, 4 ch).
    int pl = t >> 5, cg = t & 31;
    for (int pass = 0; pass < 32; pass++) {
        int p = pass*8 + pl;
        int fy = p >> 5, fx = p & 31;
        int cy = fy >> 1, cx = fx >> 1;
        const float* ap = as + p*12;
        const float* vb = vs + (cy*HX + cx)*VP + cg*4;
        ull acc0 = 0ull, acc1 = 0ull;
        #pragma unroll
        for (int dy = 0; dy < 3; dy++)
            #pragma unroll
            for (int dx = 0; dx < 3; dx++) {
                int j = dy*3 + dx;
                ull a2 = pk2(ap[j]);
                const float* vp = vb + (dy*HX + dx)*VP;
                acc0 = fma2(a2, ld2(vp),     acc0);
                acc1 = fma2(a2, ld2(vp + 2), acc1);
            }
        float2 r0 = upk(acc0), r1 = upk(acc1);
        float4 o4 = make_float4(r0.x, r0.y, r1.x, r1.y);
        *reinterpret_cast<float4*>(
            &g_x[((size_t)((b*CH + fy0 + fy)*CW + fx0 + fx))*CC + cg*4]) = o4;
    }
}

// ---------------------------------------------------------------------------
// K4: out = [Wc | Wout] @ [h_init; x] + beff. K=256, 64 px/block, f32x2 math.
// Wf transposed [k=256][o=128] pitch 130 + Ys [256][65]; smem = 199680 B
// ---------------------------------------------------------------------------
#define O_WP 130
__global__ void k_out(const float* __restrict__ hi, const float* __restrict__ Wout,
                      float* __restrict__ out) {
    extern __shared__ float sm[];
    float* Wf = sm;                 // [256][130]
    float* Ys = sm + 256*O_WP;      // [256][65]
    int t = threadIdx.x;

    for (int idx = t; idx < CC*CC; idx += 256) {
        int o = idx >> 7, i = idx & 127;
        Wf[i*O_WP + o]          = g_Wc[idx];
        Wf[(128 + i)*O_WP + o]  = Wout[idx];
    }
    int p0 = blockIdx.x * 64;
    int b = p0 / HWF, s0 = p0 % HWF;
    const float* base = hi + (size_t)b*CC*HWF + s0;
    for (int idx = t; idx < CC*64; idx += 256) {
        int c = idx >> 6, p = idx & 63;
        Ys[c*65 + p] = base[(size_t)c*HWF + p];
    }
    const float* xb = g_x + (size_t)p0*CC;
    for (int idx = t; idx < CC*64; idx += 256) {
        int c = idx & 127, p = idx >> 7;
        Ys[(CC + c)*65 + p] = xb[p*CC + c];
    }
    __syncthreads();

    int ty = t >> 4, tx = t & 15;  // ty: 16 ch-groups(8ch=4 pairs), tx: 16 px-groups(4 px)
    ull acc[4][4];
    #pragma unroll
    for (int i = 0; i < 4; i++) {
        ull binit = ld2(&g_beff[2*ty + 32*i]);
        #pragma unroll
        for (int j = 0; j < 4; j++) acc[i][j] = binit;
    }
    for (int k = 0; k < 256; k++) {
        ull yv[4];
        #pragma unroll
        for (int j = 0; j < 4; j++) yv[j] = pk2(Ys[k*65 + tx + 16*j]);
        #pragma unroll
        for (int i = 0; i < 4; i++) {
            ull wv = ld2(&Wf[k*O_WP + 2*ty + 32*i]);
            #pragma unroll
            for (int j = 0; j < 4; j++) acc[i][j] = fma2(wv, yv[j], acc[i][j]);
        }
    }

    float* ob = out + (size_t)b*CC*HWF + s0;
    #pragma unroll
    for (int i = 0; i < 4; i++) {
        int r = 2*ty + 32*i;
        #pragma unroll
        for (int j = 0; j < 4; j++) {
            float2 v = upk(acc[i][j]);
            ob[(size_t)r*HWF + tx + 16*j]       = v.x;
            ob[(size_t)(r + 1)*HWF + tx + 16*j] = v.y;
        }
    }
}

// ---------------------------------------------------------------------------
extern "C" void kernel_launch(void* const* d_in, const int* in_sizes, int n_in,
                              void* d_out, int out_size) {
    const float* h_prev = (const float*)d_in[0];
    const float* h_init = (const float*)d_in[1];
    const float* Wq   = (const float*)d_in[2];
    const float* bq   = (const float*)d_in[3];
    const float* Wk   = (const float*)d_in[4];
    const float* bk   = (const float*)d_in[5];
    const float* Wvp  = (const float*)d_in[6];
    const float* bvp  = (const float*)d_in[7];
    const float* Wvi  = (const float*)d_in[8];
    const float* bvi  = (const float*)d_in[9];
    const float* Wout = (const float*)d_in[10];
    const float* bout = (const float*)d_in[11];
    float* out = (float*)d_out;

    cudaFuncSetAttribute(k_kv,   cudaFuncAttributeMaxDynamicSharedMemorySize, 128*KV_WP*4 + 128*64*4);
    cudaFuncSetAttribute(k_q,    cudaFuncAttributeMaxDynamicSharedMemorySize, 128*Q_WP*4 + 128*64*4);
    cudaFuncSetAttribute(k_attn, cudaFuncAttributeMaxDynamicSharedMemorySize, (NH*KP + NH*VP + 256*12)*4);
    cudaFuncSetAttribute(k_out,  cudaFuncAttributeMaxDynamicSharedMemorySize, 256*O_WP*4 + 256*65*4);

    k_fuse<<<CC, CC>>>(Wout, Wvi, bvi, bout);
    k_kv<<<NPIX2/64, 256, 128*KV_WP*4 + 128*64*4>>>(h_prev, Wk, bk, Wvp, bvp);
    k_q<<<NPIXF/64, 256, 128*Q_WP*4 + 128*64*4>>>(h_init, Wq, bq);
    dim3 ag(CW2/CTX, CH2/CTY, CB);
    k_attn<<<ag, 256, (NH*KP + NH*VP + 256*12)*4>>>();
    k_out<<<NPIXF/64, 256, 256*O_WP*4 + 256*65*4>>>(h_init, Wout, out);
}